// round 6
// baseline (speedup 1.0000x reference)
#include <cuda_runtime.h>
#include <cstdint>

#define LOG2E_F 1.44269504088896340736f

constexpr int Bz = 2, SQ = 2048, SKV = 2048, HQ = 16, HKV = 4, DH = 128;
constexpr int BR = 64, BC = 64, NT = 128;

// smem float offsets
constexpr int QSTR = 136, KSTR = 136, VTSTR = 72, PSTR = 72;
constexpr int F_Q  = 0;        // 64*136 = 8704 floats
constexpr int F_KP = 8704;     // max(64*136, 64*72) = 8704 (K tile, then P overlay)
constexpr int F_VT = 17408;    // 128*72 = 9216
constexpr int F_LS = 26624;    // 128 floats
constexpr int F_TOT = 26752;
constexpr size_t SMEM_BYTES = (size_t)F_TOT * 4;   // 107008 -> 2 CTAs/SM

// packed K: [b][hk][tile64][kv(64)][136-perm]  (tf32, fragment-interleaved)
__device__ float g_kc[(size_t)Bz * HKV * (SKV / BC) * BC * KSTR];
// packed V^T: [b][hk][tile64][d(128)][72-perm(kv)]
__device__ float g_vtc[(size_t)Bz * HKV * (SKV / BC) * DH * VTSTR];

// ---------------- helpers ----------------
__device__ __forceinline__ float tf32r(float x) {
    unsigned u;
    asm("cvt.rna.tf32.f32 %0, %1;" : "=r"(u) : "f"(x));
    return __uint_as_float(u);
}
__device__ __forceinline__ float ex2f(float x) {
    float y;
    asm("ex2.approx.f32 %0, %1;" : "=f"(y) : "f"(x));
    return y;
}
__device__ __forceinline__ uint32_t smem_u32(const void* p) {
    uint32_t a;
    asm("{ .reg .u64 t; cvta.to.shared.u64 t, %1; cvt.u32.u64 %0, t; }"
        : "=r"(a) : "l"(p));
    return a;
}
__device__ __forceinline__ void cpa16(uint32_t dst, const float* src) {
    asm volatile("cp.async.cg.shared.global [%0], [%1], 16;"
                 :: "r"(dst), "l"(src));
}
__device__ __forceinline__ void cpa_commit() {
    asm volatile("cp.async.commit_group;" ::: "memory");
}
__device__ __forceinline__ void cpa_wait0() {
    asm volatile("cp.async.wait_group 0;" ::: "memory");
}
// m16n8k8 row.col tf32 mma
__device__ __forceinline__ void mma8(float* c, float2 aL, float2 aH, float2 b) {
    unsigned a0 = __float_as_uint(aL.x), a1 = __float_as_uint(aH.x);
    unsigned a2 = __float_as_uint(aL.y), a3 = __float_as_uint(aH.y);
    unsigned b0 = __float_as_uint(b.x),  b1 = __float_as_uint(b.y);
    asm volatile(
        "mma.sync.aligned.m16n8k8.row.col.f32.tf32.tf32.f32 "
        "{%0,%1,%2,%3}, {%4,%5,%6,%7}, {%8,%9}, {%0,%1,%2,%3};\n"
        : "+f"(c[0]), "+f"(c[1]), "+f"(c[2]), "+f"(c[3])
        : "r"(a0), "r"(a1), "r"(a2), "r"(a3), "r"(b0), "r"(b1));
}
// fragment-interleave position of logical k within a row (pairs k,k+4 adjacent)
__device__ __forceinline__ int kperm(int kk) {
    return (kk & ~7) + 2 * (kk & 3) + ((kk >> 2) & 1);
}

// ---------------- prepass: K pack ----------------
__global__ void kprep_kernel(const float* __restrict__ k) {
    int idx = blockIdx.x * 256 + threadIdx.x;     // one float4 each
    int d  = (idx & 31) * 4;
    int t  = idx >> 5;
    int hk = t & 3;  t >>= 2;
    int s  = t & (SKV - 1);
    int b  = t >> 11;
    float4 v4 = *(const float4*)(k + (((size_t)b * SKV + s) * HKV + hk) * DH + d);
    float* dst = g_kc + (((size_t)(b * HKV + hk) * (SKV / BC) + (s >> 6)) * BC
                         + (s & 63)) * KSTR;
    int g = (d & ~7) + ((d & 4) ? 1 : 0);
    dst[g + 0] = tf32r(v4.x);
    dst[g + 2] = tf32r(v4.y);
    dst[g + 4] = tf32r(v4.z);
    dst[g + 6] = tf32r(v4.w);
}

// ---------------- prepass: V transpose+pack ----------------
__global__ void vtprep_kernel(const float* __restrict__ v) {
    __shared__ float t[64][33];
    const int kvt = blockIdx.x;          // kv tile (64 wide)
    const int d0  = blockIdx.y * 32;
    const int bh  = blockIdx.z;          // b*HKV+hk
    const int b = bh >> 2, hk = bh & 3;
    const int tx = threadIdx.x, ty = threadIdx.y;   // 32 x 8
    const float* src = v + ((size_t)b * SKV * HKV + hk) * DH + d0;
    #pragma unroll
    for (int i = 0; i < 8; ++i) {
        int kvl = ty + 8 * i;
        t[kvl][tx] = src[(size_t)(kvt * 64 + kvl) * (HKV * DH) + tx];
    }
    __syncthreads();
    float* dst = g_vtc + ((size_t)bh * (SKV / BC) + kvt) * (DH * VTSTR)
               + (size_t)d0 * VTSTR;
    #pragma unroll
    for (int i = 0; i < 8; ++i) {
        int e = i * 256 + ty * 32 + tx;
        int dl = e >> 6, kvl = e & 63;
        dst[dl * VTSTR + kperm(kvl)] = tf32r(t[kvl][dl]);
    }
}

// ---------------- main attention kernel ----------------
__global__ void __launch_bounds__(NT, 2)
fa_kernel(const float* __restrict__ q,
          const float* __restrict__ mask,
          float* __restrict__ out)
{
    extern __shared__ float sm[];
    const uint32_t sb = smem_u32(sm);

    const int tid = threadIdx.x;
    const int w = tid >> 5;            // 4 warps
    const int lane = tid & 31;
    const int qgrp = lane >> 2;
    const int qid  = lane & 3;
    const int mg = w >> 1;             // m-group: rows mg*32 .. +31
    const int nh = w & 1;              // n-half (S: 32-col half; O: 64-d half)

    const int bx = blockIdx.x;
    const int q0 = bx * BR;
    const int h  = blockIdx.y;
    const int b  = blockIdx.z;
    const int hk = h & (HKV - 1);
    const int bh = b * HKV + hk;
    const int ntiles = bx + 1;

    const uint32_t KPB = sb + F_KP * 4u;
    const uint32_t VTB = sb + F_VT * 4u;

    // ---- Q tile: LDG + scale + tf32 + interleaved STS ----
    {
        const float qscale = LOG2E_F * 0.08838834764831845f;  // log2e/sqrt(128)
        const float* qb = q + (((size_t)b * SQ + q0) * HQ + h) * DH;
        #pragma unroll
        for (int i = 0; i < 16; ++i) {
            int f4 = tid + NT * i;
            int row = f4 >> 5;
            int c = (f4 & 31) << 2;
            float4 v4 = *(const float4*)(qb + (size_t)row * (HQ * DH) + c);
            int g = (c & ~7) + ((c & 4) ? 1 : 0);
            float* dst = sm + F_Q + row * QSTR;
            dst[g + 0] = tf32r(v4.x * qscale);
            dst[g + 2] = tf32r(v4.y * qscale);
            dst[g + 4] = tf32r(v4.z * qscale);
            dst[g + 6] = tf32r(v4.w * qscale);
        }
    }

    const int rl0 = mg * 32 + qgrp;
    const float* mp[2][2];
    #pragma unroll
    for (int mi = 0; mi < 2; ++mi)
        #pragma unroll
        for (int hb = 0; hb < 2; ++hb) {
            int rg = q0 + rl0 + mi * 16 + hb * 8;
            mp[mi][hb] = mask + ((size_t)(b * HQ + h) * SQ + rg) * SKV;
        }

    float O[2][8][4];
    #pragma unroll
    for (int mi = 0; mi < 2; ++mi)
        #pragma unroll
        for (int nt = 0; nt < 8; ++nt) {
            O[mi][nt][0] = 0.f; O[mi][nt][1] = 0.f;
            O[mi][nt][2] = 0.f; O[mi][nt][3] = 0.f;
        }
    float ls[2][2] = {{0.f, 0.f}, {0.f, 0.f}};
    const int pp = ((qid & 1) << 2) + (qid >> 1);  // P-store perm base

    for (int j = 0; j < ntiles; ++j) {
        const int kv0 = j * BC;

        __syncthreads();               // A: prev MMA2 done; K/V buffers free
        {
            const float* ks = g_kc + ((size_t)bh * (SKV / BC) + j) * (BC * KSTR);
            const float* vs = g_vtc + ((size_t)bh * (SKV / BC) + j) * (DH * VTSTR);
            #pragma unroll
            for (int i = 0; i < 18; ++i) {
                int idx = tid + NT * i;
                if (idx < BC * KSTR / 4)  cpa16(KPB + idx * 16, ks + idx * 4);
                if (idx < DH * VTSTR / 4) cpa16(VTB + idx * 16, vs + idx * 4);
            }
        }
        cpa_commit();
        cpa_wait0();
        __syncthreads();               // B: tile j visible to all warps

        // ---- mask prefetch into registers (latency hidden by MMA1) ----
        float2 mk[2][2][4];
        #pragma unroll
        for (int mi = 0; mi < 2; ++mi)
            #pragma unroll
            for (int hb = 0; hb < 2; ++hb)
                #pragma unroll
                for (int nt = 0; nt < 4; ++nt)
                    mk[mi][hb][nt] = *(const float2*)(
                        mp[mi][hb] + kv0 + nh * 32 + nt * 8 + 2 * qid);

        // ---- MMA1: S(m32 x n32) = Q @ K^T ----
        float S[2][4][4];
        #pragma unroll
        for (int mi = 0; mi < 2; ++mi)
            #pragma unroll
            for (int nt = 0; nt < 4; ++nt) {
                S[mi][nt][0] = 0.f; S[mi][nt][1] = 0.f;
                S[mi][nt][2] = 0.f; S[mi][nt][3] = 0.f;
            }
        {
            const float* Ks = sm + F_KP;
            #pragma unroll
            for (int kt = 0; kt < 16; ++kt) {
                const int ko = kt * 8 + 2 * qid;
                float2 a0L = *(const float2*)(sm + F_Q + (rl0)      * QSTR + ko);
                float2 a0H = *(const float2*)(sm + F_Q + (rl0 + 8)  * QSTR + ko);
                float2 a1L = *(const float2*)(sm + F_Q + (rl0 + 16) * QSTR + ko);
                float2 a1H = *(const float2*)(sm + F_Q + (rl0 + 24) * QSTR + ko);
                #pragma unroll
                for (int nt = 0; nt < 4; ++nt) {
                    float2 bb = *(const float2*)(Ks + (nh * 32 + nt * 8 + qgrp) * KSTR + ko);
                    mma8(S[0][nt], a0L, a0H, bb);
                    mma8(S[1][nt], a1L, a1H, bb);
                }
            }
        }
        __syncthreads();               // C: all K reads done, buffer reusable for P

        // ---- softmax + P store (overlays K buffer) ----
        {
            float* Ps = sm + F_KP;
            #pragma unroll
            for (int mi = 0; mi < 2; ++mi) {
                const int rgl0 = q0 + rl0 + mi * 16;
                #pragma unroll
                for (int nt = 0; nt < 4; ++nt) {
                    const int c0 = kv0 + nh * 32 + nt * 8 + 2 * qid;
                    float2 mk0 = mk[mi][0][nt];
                    float2 mk1 = mk[mi][1][nt];
                    float p00 = (c0     <= rgl0)     ? ex2f(S[mi][nt][0] + LOG2E_F * mk0.x) : 0.f;
                    float p01 = (c0 + 1 <= rgl0)     ? ex2f(S[mi][nt][1] + LOG2E_F * mk0.y) : 0.f;
                    float p10 = (c0     <= rgl0 + 8) ? ex2f(S[mi][nt][2] + LOG2E_F * mk1.x) : 0.f;
                    float p11 = (c0 + 1 <= rgl0 + 8) ? ex2f(S[mi][nt][3] + LOG2E_F * mk1.y) : 0.f;
                    ls[mi][0] += p00 + p01;
                    ls[mi][1] += p10 + p11;
                    float* pr0 = Ps + (rl0 + mi * 16) * PSTR + nh * 32 + nt * 8;
                    float* pr1 = pr0 + 8 * PSTR;
                    pr0[pp]     = tf32r(p00);
                    pr0[pp + 2] = tf32r(p01);
                    pr1[pp]     = tf32r(p10);
                    pr1[pp + 2] = tf32r(p11);
                }
            }
        }
        __syncthreads();               // D: P complete

        // ---- MMA2: O(m32 x d64) += P @ V ----
        {
            const float* Ps = sm + F_KP;
            const float* Vs = sm + F_VT;
            #pragma unroll
            for (int kt = 0; kt < 8; ++kt) {
                const int ko = kt * 8 + 2 * qid;
                float2 a0L = *(const float2*)(Ps + (rl0)      * PSTR + ko);
                float2 a0H = *(const float2*)(Ps + (rl0 + 8)  * PSTR + ko);
                float2 a1L = *(const float2*)(Ps + (rl0 + 16) * PSTR + ko);
                float2 a1H = *(const float2*)(Ps + (rl0 + 24) * PSTR + ko);
                #pragma unroll
                for (int nt = 0; nt < 8; ++nt) {
                    float2 bb = *(const float2*)(Vs + (nh * 64 + nt * 8 + qgrp) * VTSTR + ko);
                    mma8(O[0][nt], a0L, a0H, bb);
                    mma8(O[1][nt], a1L, a1H, bb);
                }
            }
        }
    }

    // ---- row sums: reduce over qid lanes, then across nh halves via smem ----
    #pragma unroll
    for (int mi = 0; mi < 2; ++mi)
        #pragma unroll
        for (int hb = 0; hb < 2; ++hb) {
            float s = ls[mi][hb];
            s += __shfl_xor_sync(0xffffffffu, s, 1);
            s += __shfl_xor_sync(0xffffffffu, s, 2);
            ls[mi][hb] = s;
        }
    if (qid == 0) {
        float* LS = sm + F_LS;
        #pragma unroll
        for (int mi = 0; mi < 2; ++mi)
            #pragma unroll
            for (int hb = 0; hb < 2; ++hb)
                LS[nh * 64 + rl0 + mi * 16 + hb * 8] = ls[mi][hb];
    }
    __syncthreads();

    const float* LS = sm + F_LS;
    #pragma unroll
    for (int mi = 0; mi < 2; ++mi) {
        #pragma unroll
        for (int hb = 0; hb < 2; ++hb) {
            const int rl = rl0 + mi * 16 + hb * 8;
            const float inv = 1.0f / (LS[rl] + LS[64 + rl]);
            const int rg = q0 + rl;
            float* orow = out + (((size_t)b * SQ + rg) * HQ + h) * DH + nh * 64;
            #pragma unroll
            for (int nt = 0; nt < 8; ++nt) {
                float x = O[mi][nt][hb * 2 + 0] * inv;
                float y = O[mi][nt][hb * 2 + 1] * inv;
                *(float2*)(orow + nt * 8 + 2 * qid) = make_float2(x, y);
            }
        }
    }
}

extern "C" void kernel_launch(void* const* d_in, const int* in_sizes, int n_in,
                              void* d_out, int out_size) {
    (void)in_sizes; (void)n_in; (void)out_size;
    const float* q = (const float*)d_in[0];
    const float* k = (const float*)d_in[1];
    const float* v = (const float*)d_in[2];
    const float* mask = (const float*)d_in[3];
    float* out = (float*)d_out;

    cudaFuncSetAttribute(fa_kernel,
                         cudaFuncAttributeMaxDynamicSharedMemorySize,
                         (int)SMEM_BYTES);

    kprep_kernel<<<(Bz * SKV * HKV * DH / 4) / 256, 256>>>(k);
    vtprep_kernel<<<dim3(SKV / BC, DH / 32, Bz * HKV), dim3(32, 8)>>>(v);
    fa_kernel<<<dim3(SQ / BR, HQ, Bz), NT, SMEM_BYTES>>>(q, mask, out);
}

// round 7
// speedup vs baseline: 1.7033x; 1.7033x over previous
#include <cuda_runtime.h>
#include <cstdint>

#define LOG2E_F 1.44269504088896340736f

constexpr int Bz = 2, SQ = 2048, SKV = 2048, HQ = 16, HKV = 4, DH = 128;
constexpr int BR = 128, BC = 64, NT = 256;

// smem float offsets (double-buffered K and V^T)
constexpr int QSTR = 136, KSTR = 136, VTSTR = 72;
constexpr int F_Q  = 0;                  // 128*136 = 17408
constexpr int F_K0 = 17408;              // 64*136  = 8704
constexpr int F_K1 = F_K0 + 8704;
constexpr int F_V0 = F_K1 + 8704;        // 128*72  = 9216
constexpr int F_V1 = F_V0 + 9216;
constexpr int F_TOT = F_V1 + 9216;       // 53248 floats
constexpr size_t SMEM_BYTES = (size_t)F_TOT * 4;   // 212992 B (1 CTA/SM)

// packed K: [b][hk][tile64][kv(64)][136] tf32, k-pair interleaved for fragments
__device__ float g_kc[(size_t)Bz * HKV * (SKV / BC) * BC * KSTR];
// packed V^T: [b][hk][tile64][d(128)][72] tf32, kv contiguous (NO perm)
__device__ float g_vtc[(size_t)Bz * HKV * (SKV / BC) * DH * VTSTR];

// ---------------- helpers ----------------
__device__ __forceinline__ float tf32r(float x) {
    unsigned u;
    asm("cvt.rna.tf32.f32 %0, %1;" : "=r"(u) : "f"(x));
    return __uint_as_float(u);
}
__device__ __forceinline__ float ex2f(float x) {
    float y;
    asm("ex2.approx.f32 %0, %1;" : "=f"(y) : "f"(x));
    return y;
}
__device__ __forceinline__ uint32_t smem_u32(const void* p) {
    uint32_t a;
    asm("{ .reg .u64 t; cvta.to.shared.u64 t, %1; cvt.u32.u64 %0, t; }"
        : "=r"(a) : "l"(p));
    return a;
}
__device__ __forceinline__ void cpa16(uint32_t dst, const float* src) {
    asm volatile("cp.async.cg.shared.global [%0], [%1], 16;"
                 :: "r"(dst), "l"(src));
}
__device__ __forceinline__ void cpa_commit() {
    asm volatile("cp.async.commit_group;" ::: "memory");
}
__device__ __forceinline__ void cpa_wait1() {
    asm volatile("cp.async.wait_group 1;" ::: "memory");
}
// m16n8k8 row.col tf32 mma.  a0=aL.x a1=aH.x a2=aL.y a3=aH.y
__device__ __forceinline__ void mma8(float* c, float2 aL, float2 aH, float2 b) {
    unsigned a0 = __float_as_uint(aL.x), a1 = __float_as_uint(aH.x);
    unsigned a2 = __float_as_uint(aL.y), a3 = __float_as_uint(aH.y);
    unsigned b0 = __float_as_uint(b.x),  b1 = __float_as_uint(b.y);
    asm volatile(
        "mma.sync.aligned.m16n8k8.row.col.f32.tf32.tf32.f32 "
        "{%0,%1,%2,%3}, {%4,%5,%6,%7}, {%8,%9}, {%0,%1,%2,%3};\n"
        : "+f"(c[0]), "+f"(c[1]), "+f"(c[2]), "+f"(c[3])
        : "r"(a0), "r"(a1), "r"(a2), "r"(a3), "r"(b0), "r"(b1));
}

// ---------------- prepass: K pack (fragment k-pair interleave) ----------------
__global__ void kprep_kernel(const float* __restrict__ k) {
    int idx = blockIdx.x * 256 + threadIdx.x;     // one float4 each
    int d  = (idx & 31) * 4;
    int t  = idx >> 5;
    int hk = t & 3;  t >>= 2;
    int s  = t & (SKV - 1);
    int b  = t >> 11;
    float4 v4 = *(const float4*)(k + (((size_t)b * SKV + s) * HKV + hk) * DH + d);
    float* dst = g_kc + (((size_t)(b * HKV + hk) * (SKV / BC) + (s >> 6)) * BC
                         + (s & 63)) * KSTR;
    int g = (d & ~7) + ((d & 4) ? 1 : 0);
    dst[g + 0] = tf32r(v4.x);
    dst[g + 2] = tf32r(v4.y);
    dst[g + 4] = tf32r(v4.z);
    dst[g + 6] = tf32r(v4.w);
}

// ---------------- prepass: V transpose+pack (plain kv order) ----------------
__global__ void vtprep_kernel(const float* __restrict__ v) {
    __shared__ float t[64][33];
    const int kvt = blockIdx.x;          // kv tile (64 wide)
    const int d0  = blockIdx.y * 32;
    const int bh  = blockIdx.z;          // b*HKV+hk
    const int b = bh >> 2, hk = bh & 3;
    const int tx = threadIdx.x, ty = threadIdx.y;   // 32 x 8
    const float* src = v + ((size_t)b * SKV * HKV + hk) * DH + d0;
    #pragma unroll
    for (int i = 0; i < 8; ++i) {
        int kvl = ty + 8 * i;
        t[kvl][tx] = src[(size_t)(kvt * 64 + kvl) * (HKV * DH) + tx];
    }
    __syncthreads();
    float* dst = g_vtc + ((size_t)bh * (SKV / BC) + kvt) * (DH * VTSTR)
               + (size_t)d0 * VTSTR;
    #pragma unroll
    for (int i = 0; i < 8; ++i) {
        int e = i * 256 + ty * 32 + tx;
        int dl = e >> 6, kvl = e & 63;
        dst[dl * VTSTR + kvl] = tf32r(t[kvl][dl]);
    }
}

// ---------------- main attention kernel ----------------
__global__ void __launch_bounds__(NT, 1)
fa_kernel(const float* __restrict__ q,
          const float* __restrict__ mask,
          float* __restrict__ out)
{
    extern __shared__ float sm[];
    const uint32_t sb = smem_u32(sm);

    const int tid = threadIdx.x;
    const int w = tid >> 5;            // 8 warps, warp owns rows w*16..w*16+15
    const int lane = tid & 31;
    const int qgrp = lane >> 2;
    const int qid  = lane & 3;

    const int bx = blockIdx.x;
    const int q0 = bx * BR;
    const int h  = blockIdx.y;
    const int b  = blockIdx.z;
    const int hk = h & (HKV - 1);
    const int bh = b * HKV + hk;
    const int ntiles = 2 * bx + 2;

    const uint32_t KB[2] = { sb + F_K0 * 4u, sb + F_K1 * 4u };
    const uint32_t VB[2] = { sb + F_V0 * 4u, sb + F_V1 * 4u };
    const float* kc0 = g_kc + (size_t)bh * (SKV / BC) * (BC * KSTR);
    const float* vc0 = g_vtc + (size_t)bh * (SKV / BC) * (DH * VTSTR);

    // ---- prologue: prefetch tiles 0 and 1 (two cp.async groups) ----
    #pragma unroll
    for (int tpre = 0; tpre < 2; ++tpre) {
        const float* ks = kc0 + (size_t)tpre * (BC * KSTR);
        const float* vs = vc0 + (size_t)tpre * (DH * VTSTR);
        #pragma unroll
        for (int i = 0; i < 9; ++i) {
            int idx = tid + NT * i;
            if (idx < BC * KSTR / 4)  cpa16(KB[tpre] + idx * 16, ks + idx * 4);
            if (idx < DH * VTSTR / 4) cpa16(VB[tpre] + idx * 16, vs + idx * 4);
        }
        cpa_commit();
    }

    // ---- Q tile: LDG + scale + tf32 + interleaved STS (overlaps prefetch) ----
    {
        const float qscale = LOG2E_F * 0.08838834764831845f;  // log2e/sqrt(128)
        const float* qb = q + (((size_t)b * SQ + q0) * HQ + h) * DH;
        #pragma unroll
        for (int i = 0; i < 16; ++i) {
            int f4 = tid + NT * i;
            int row = f4 >> 5;
            int c = (f4 & 31) << 2;
            float4 v4 = *(const float4*)(qb + (size_t)row * (HQ * DH) + c);
            int g = (c & ~7) + ((c & 4) ? 1 : 0);
            float* dst = sm + F_Q + row * QSTR;
            dst[g + 0] = tf32r(v4.x * qscale);
            dst[g + 2] = tf32r(v4.y * qscale);
            dst[g + 4] = tf32r(v4.z * qscale);
            dst[g + 6] = tf32r(v4.w * qscale);
        }
    }

    const int rg0 = q0 + w * 16 + qgrp;      // global row (and rg0+8)
    const int rwmax = q0 + w * 16 + 15;      // causal warp bound
    const float* mrow0 = mask + ((size_t)(b * HQ + h) * SQ + rg0) * SKV;
    const float* mrow1 = mrow0 + (size_t)8 * SKV;
    const float* qrow0 = sm + F_Q + (w * 16 + qgrp) * QSTR;
    const float* qrow1 = qrow0 + 8 * QSTR;

    float O[16][4];
    #pragma unroll
    for (int nt = 0; nt < 16; ++nt) {
        O[nt][0] = 0.f; O[nt][1] = 0.f; O[nt][2] = 0.f; O[nt][3] = 0.f;
    }
    float ls0 = 0.f, ls1 = 0.f;

    for (int j = 0; j < ntiles; ++j) {
        const int kv0 = j * BC;
        const int cur = j & 1;

        cpa_wait1();                    // tile j resident (j+1 may be in flight)
        __syncthreads();                // all threads' copies of tile j visible

        if (kv0 <= rwmax) {
            // ---- mask prefetch into registers (hidden under MMA1) ----
            float2 mk0[8], mk1[8];
            #pragma unroll
            for (int nt = 0; nt < 8; ++nt) {
                mk0[nt] = *(const float2*)(mrow0 + kv0 + nt * 8 + 2 * qid);
                mk1[nt] = *(const float2*)(mrow1 + kv0 + nt * 8 + 2 * qid);
            }

            // ---- MMA1: S(m16 x n64) = Q @ K^T ----
            float S[8][4];
            #pragma unroll
            for (int nt = 0; nt < 8; ++nt) {
                S[nt][0] = 0.f; S[nt][1] = 0.f; S[nt][2] = 0.f; S[nt][3] = 0.f;
            }
            {
                const float* Ks = sm + (cur ? F_K1 : F_K0);
                #pragma unroll
                for (int kt = 0; kt < 16; ++kt) {
                    const int ko = kt * 8 + 2 * qid;
                    float2 aL = *(const float2*)(qrow0 + ko);
                    float2 aH = *(const float2*)(qrow1 + ko);
                    #pragma unroll
                    for (int nt = 0; nt < 8; ++nt) {
                        float2 bb = *(const float2*)(Ks + (nt * 8 + qgrp) * KSTR + ko);
                        mma8(S[nt], aL, aH, bb);
                    }
                }
            }

            // ---- softmax: P = exp2(S + mask*log2e), causal-zeroed, in regs ----
            #pragma unroll
            for (int nt = 0; nt < 8; ++nt) {
                const int c0 = kv0 + nt * 8 + 2 * qid;
                float p00 = (c0     <= rg0)     ? ex2f(S[nt][0] + LOG2E_F * mk0[nt].x) : 0.f;
                float p01 = (c0 + 1 <= rg0)     ? ex2f(S[nt][1] + LOG2E_F * mk0[nt].y) : 0.f;
                float p10 = (c0     <= rg0 + 8) ? ex2f(S[nt][2] + LOG2E_F * mk1[nt].x) : 0.f;
                float p11 = (c0 + 1 <= rg0 + 8) ? ex2f(S[nt][3] + LOG2E_F * mk1[nt].y) : 0.f;
                ls0 += p00 + p01;
                ls1 += p10 + p11;
                S[nt][0] = tf32r(p00);
                S[nt][1] = tf32r(p01);
                S[nt][2] = tf32r(p10);
                S[nt][3] = tf32r(p11);
            }

            // ---- MMA2: O(m16 x d128) += P @ V, P straight from registers ----
            // C-frag cols {2q,2q+1} are actual kv; V^T float2 at kv=kt*8+2q
            // supplies (b0,b1) for the same kv — layouts line up with A=(c0,c2,c1,c3).
            {
                const float* Vs = sm + (cur ? F_V1 : F_V0);
                #pragma unroll
                for (int kt = 0; kt < 8; ++kt) {
                    float2 aL = make_float2(S[kt][0], S[kt][1]);
                    float2 aH = make_float2(S[kt][2], S[kt][3]);
                    #pragma unroll
                    for (int nt = 0; nt < 16; ++nt) {
                        float2 bb = *(const float2*)(Vs + (nt * 8 + qgrp) * VTSTR
                                                     + kt * 8 + 2 * qid);
                        mma8(O[nt], aL, aH, bb);
                    }
                }
            }
        }

        __syncthreads();                // all warps done with buffer `cur`
        if (j + 2 < ntiles) {
            const float* ks = kc0 + (size_t)(j + 2) * (BC * KSTR);
            const float* vs = vc0 + (size_t)(j + 2) * (DH * VTSTR);
            #pragma unroll
            for (int i = 0; i < 9; ++i) {
                int idx = tid + NT * i;
                if (idx < BC * KSTR / 4)  cpa16(KB[cur] + idx * 16, ks + idx * 4);
                if (idx < DH * VTSTR / 4) cpa16(VB[cur] + idx * 16, vs + idx * 4);
            }
        }
        cpa_commit();                   // commit (possibly empty) group
    }

    // ---- row sums (reduce over qid lanes), normalize, store ----
    ls0 += __shfl_xor_sync(0xffffffffu, ls0, 1);
    ls0 += __shfl_xor_sync(0xffffffffu, ls0, 2);
    ls1 += __shfl_xor_sync(0xffffffffu, ls1, 1);
    ls1 += __shfl_xor_sync(0xffffffffu, ls1, 2);
    const float inv0 = 1.0f / ls0;
    const float inv1 = 1.0f / ls1;

    float* o0 = out + (((size_t)b * SQ + rg0) * HQ + h) * DH;
    float* o1 = o0 + (size_t)8 * HQ * DH;
    #pragma unroll
    for (int nt = 0; nt < 16; ++nt) {
        const int c = nt * 8 + 2 * qid;
        *(float2*)(o0 + c) = make_float2(O[nt][0] * inv0, O[nt][1] * inv0);
        *(float2*)(o1 + c) = make_float2(O[nt][2] * inv1, O[nt][3] * inv1);
    }
}

extern "C" void kernel_launch(void* const* d_in, const int* in_sizes, int n_in,
                              void* d_out, int out_size) {
    (void)in_sizes; (void)n_in; (void)out_size;
    const float* q = (const float*)d_in[0];
    const float* k = (const float*)d_in[1];
    const float* v = (const float*)d_in[2];
    const float* mask = (const float*)d_in[3];
    float* out = (float*)d_out;

    cudaFuncSetAttribute(fa_kernel,
                         cudaFuncAttributeMaxDynamicSharedMemorySize,
                         (int)SMEM_BYTES);

    kprep_kernel<<<(Bz * SKV * HKV * DH / 4) / 256, 256>>>(k);
    vtprep_kernel<<<dim3(SKV / BC, DH / 32, Bz * HKV), dim3(32, 8)>>>(v);
    fa_kernel<<<dim3(SQ / BR, HQ, Bz), NT, SMEM_BYTES>>>(q, mask, out);
}